// round 8
// baseline (speedup 1.0000x reference)
#include <cuda_runtime.h>
#include <cuda_bf16.h>
#include <math.h>

// ---------------- problem constants ----------------
#define Bsz   16
#define Ssz   512
#define DE    100
#define DT    20
#define DI    20
#define INs   140     // DE+DT+DI
#define Hh    128
#define GD    256     // 2*H
#define G4    512     // 4*H
#define Nn    128     // nodes
#define Ee    48      // entities
#define Pp    512     // pairs
#define Rr    97      // relations
#define BANK  768     // GD*(ITERS+1)
#define CLSZ  1556    // BANK*2 + 20
#define HID   1536    // BANK*2

// ---------------- device scratch (static; no allocations allowed) ----------------
__device__ float g_X[Ssz * Bsz * INs];              // [s][b][in]
__device__ float g_XG[2ll * Ssz * Bsz * G4];        // [dir][s][b][4H]  (x@Wih^T + bias)
__device__ float g_W4[2 * Hh * G4];                 // [dir][k][d][gate] packed
__device__ float g_enc[(size_t)Bsz * Ssz * GD];     // [b][s][2H]
__device__ float g_cs[(size_t)Bsz * (Ssz + 1) * GD];// cumsum (masked)
__device__ float g_feat[(size_t)Bsz * Nn * BANK];   // [gfea | h1 | h2]
__device__ float g_Anorm[(size_t)Bsz * Nn * Nn];
__device__ float g_tmp[(size_t)Bsz * Nn * GD];      // GCN aggregate scratch
__device__ float g_bank[(size_t)Bsz * Ee * BANK];
__device__ float g_rel[(size_t)Bsz * Pp * CLSZ];
__device__ float g_hid[(size_t)Bsz * Pp * HID];

__device__ __forceinline__ float sigmoidf_(float x) { return 1.f / (1.f + expf(-x)); }

// ---------------- 1. embedding concat ----------------
__global__ void embed_kernel(const int* __restrict__ words,
                             const int* __restrict__ etype,
                             const int* __restrict__ eid,
                             const float* __restrict__ wtab,
                             const float* __restrict__ ttab,
                             const float* __restrict__ itab)
{
    int idx = blockIdx.x * blockDim.x + threadIdx.x;
    int total = Ssz * Bsz * INs;
    if (idx >= total) return;
    int c = idx % INs;
    int sb = idx / INs;
    int b = sb % Bsz;
    int s = sb / Bsz;
    float v;
    if (c < DE)            v = wtab[(size_t)words[b * Ssz + s] * DE + c];
    else if (c < DE + DT)  v = ttab[etype[b * Ssz + s] * DT + (c - DE)];
    else                   v = itab[eid[b * Ssz + s] * DI + (c - DE - DT)];
    g_X[idx] = v;
}

// ---------------- 2. generic SGEMM: C = act(A(MxK) * B + bias) ----------------
// transB==1: B stored [N,K] (use W^T);  transB==0: B stored [K,N]
// act: 0 none, 1 tanh, 2 relu
// Double-buffered smem, register-staged prefetch, one barrier per K-tile,
// conflict-free 4+4 split fragment mapping, vectorized LDG.128 fetch,
// vectorized STG.128 epilogue when ldc allows.
#define BM 128
#define BN 128
#define BKs 8
#define SP 132   // smem row stride (pad kills STS conflicts; keeps 16B align)
__global__ __launch_bounds__(256, 2)
void sgemm_kernel(const float* __restrict__ A, int lda,
                  const float* __restrict__ Bm,
                  const float* __restrict__ bias,
                  float* __restrict__ C, int ldc,
                  int M, int Nc, int K, int transB, int act)
{
    __shared__ float As[2][BKs][SP];
    __shared__ float Bs[2][BKs][SP];
    int tid = threadIdx.x;
    int tx = tid & 15, ty = tid >> 4;
    int row0 = blockIdx.y * BM, col0 = blockIdx.x * BN;
    float acc[8][8];
#pragma unroll
    for (int i = 0; i < 8; i++)
#pragma unroll
        for (int j = 0; j < 8; j++) acc[i][j] = 0.f;

    // A-load (and B-load when transB=1): float4 along K
    int ar  = tid >> 1;          // 0..127 tile row
    int ak4 = (tid & 1) * 4;     // 0 or 4
    int gr  = row0 + ar;         // A global row
    int gnr = col0 + ar;         // B global row (transB=1)
    // B-load (transB=0): float4 along N
    int bk  = tid >> 5;          // 0..7  (k within tile)
    int bn4 = (tid & 31) * 4;    // 0..124

    float pa[4], pb[4];

    auto fetch = [&](int k0) {
        // ---- A ----
        if (gr < M && k0 + ak4 + 3 < K) {
            float4 v = *(const float4*)(A + (size_t)gr * lda + k0 + ak4);
            pa[0] = v.x; pa[1] = v.y; pa[2] = v.z; pa[3] = v.w;
        } else {
#pragma unroll
            for (int u = 0; u < 4; u++) {
                int gk = k0 + ak4 + u;
                pa[u] = (gr < M && gk < K) ? A[(size_t)gr * lda + gk] : 0.f;
            }
        }
        // ---- B ----
        if (transB) {
            if (gnr < Nc && k0 + ak4 + 3 < K) {
                float4 v = *(const float4*)(Bm + (size_t)gnr * K + k0 + ak4);
                pb[0] = v.x; pb[1] = v.y; pb[2] = v.z; pb[3] = v.w;
            } else {
#pragma unroll
                for (int u = 0; u < 4; u++) {
                    int gk = k0 + ak4 + u;
                    pb[u] = (gnr < Nc && gk < K) ? Bm[(size_t)gnr * K + gk] : 0.f;
                }
            }
        } else {
            int gk = k0 + bk;
            int gc = col0 + bn4;
            if (gk < K && (Nc & 3) == 0 && gc + 3 < Nc) {
                float4 v = *(const float4*)(Bm + (size_t)gk * Nc + gc);
                pb[0] = v.x; pb[1] = v.y; pb[2] = v.z; pb[3] = v.w;
            } else {
#pragma unroll
                for (int u = 0; u < 4; u++) {
                    int c = gc + u;
                    pb[u] = (gk < K && c < Nc) ? Bm[(size_t)gk * Nc + c] : 0.f;
                }
            }
        }
    };
    auto stage = [&](int buf) {
#pragma unroll
        for (int u = 0; u < 4; u++) As[buf][ak4 + u][ar] = pa[u];
        if (transB) {
#pragma unroll
            for (int u = 0; u < 4; u++) Bs[buf][ak4 + u][ar] = pb[u];
        } else {
            *(float4*)&Bs[buf][bk][bn4] = make_float4(pb[0], pb[1], pb[2], pb[3]);
        }
    };

    // prologue: tile 0 resident in buf 0; tile 1 in-flight in registers
    fetch(0);
    stage(0);
    __syncthreads();
    fetch(BKs);   // predicated-safe past K

    int cur = 0;
    for (int k0 = 0; k0 < K; k0 += BKs) {
#pragma unroll
        for (int kk = 0; kk < BKs; kk++) {
            float4 a0 = *(const float4*)&As[cur][kk][ty * 4];
            float4 a1 = *(const float4*)&As[cur][kk][64 + ty * 4];
            float4 b0 = *(const float4*)&Bs[cur][kk][tx * 4];
            float4 b1 = *(const float4*)&Bs[cur][kk][64 + tx * 4];
            float ra[8] = {a0.x, a0.y, a0.z, a0.w, a1.x, a1.y, a1.z, a1.w};
            float rb[8] = {b0.x, b0.y, b0.z, b0.w, b1.x, b1.y, b1.z, b1.w};
#pragma unroll
            for (int i = 0; i < 8; i++)
#pragma unroll
                for (int j = 0; j < 8; j++)
                    acc[i][j] = fmaf(ra[i], rb[j], acc[i][j]);
        }
        if (k0 + BKs < K) {
            stage(cur ^ 1);        // other buffer; its readers finished before
            __syncthreads();       //   the PREVIOUS barrier
            fetch(k0 + 2 * BKs);   // overlap next-next loads with compute
            cur ^= 1;
        }
    }
    // epilogue: two 4-contiguous column runs per row -> STG.128 when possible
    bool vec_st = ((ldc & 3) == 0);
#pragma unroll
    for (int i = 0; i < 8; i++) {
        int rr = row0 + (i < 4 ? ty * 4 + i : 64 + ty * 4 + i - 4);
        if (rr >= M) continue;
#pragma unroll
        for (int jh = 0; jh < 2; jh++) {
            int cc = col0 + jh * 64 + tx * 4;
            float r[4];
#pragma unroll
            for (int u = 0; u < 4; u++) {
                float v = acc[i][jh * 4 + u] + ((cc + u < Nc) ? bias[cc + u] : 0.f);
                if (act == 1) v = tanhf(v);
                else if (act == 2) v = fmaxf(v, 0.f);
                r[u] = v;
            }
            if (vec_st && cc + 3 < Nc) {
                *(float4*)(C + (size_t)rr * ldc + cc) = make_float4(r[0], r[1], r[2], r[3]);
            } else {
#pragma unroll
                for (int u = 0; u < 4; u++)
                    if (cc + u < Nc) C[(size_t)rr * ldc + cc + u] = r[u];
            }
        }
    }
}

// ---------------- 3. Whh pack: g_W4[dir][k][d][g] = Whh[dir][g*128+d][k] ----------------
__global__ void pack_whh_kernel(const float* __restrict__ Whh_f,
                                const float* __restrict__ Whh_b)
{
    int idx = blockIdx.x * blockDim.x + threadIdx.x; // 2 * 128 * 512
    if (idx >= 2 * Hh * G4) return;
    int g = idx & 3;
    int d = (idx >> 2) & (Hh - 1);
    int k = (idx >> 9) & (Hh - 1);
    int dir = idx >> 16;
    const float* W = dir ? Whh_b : Whh_f;
    g_W4[idx] = W[(size_t)(g * Hh + d) * Hh + k];
}

// ---------------- 4. LSTM recurrence ----------------
// One block per (dir, batch-pair). 128 threads; thread d owns h-dim d
// (all 4 gates) for 2 batches. W is gate-interleaved -> one LDG.128 per k.
__global__ __launch_bounds__(128)
void lstm_kernel()
{
    int dir = blockIdx.y;          // 0 fwd, 1 bwd
    int b0 = blockIdx.x * 2;       // batch group
    int d = threadIdx.x;           // 0..127 (h dim)
    __shared__ float h_sh[2][2][Hh];   // [buf][batch][k]
    float c_reg0 = 0.f, c_reg1 = 0.f;
    h_sh[0][0][d] = 0.f;
    h_sh[0][1][d] = 0.f;
    __syncthreads();

    const float4* __restrict__ W = ((const float4*)g_W4) + (size_t)dir * Hh * Hh;
    int cur = 0;
    for (int t = 0; t < Ssz; t++) {
        int s = dir ? (Ssz - 1 - t) : t;
        const float* __restrict__ xg =
            g_XG + (((size_t)dir * Ssz + s) * Bsz + b0) * G4;
        float a00 = xg[0 * Hh + d];
        float a01 = xg[1 * Hh + d];
        float a02 = xg[2 * Hh + d];
        float a03 = xg[3 * Hh + d];
        float a10 = xg[G4 + 0 * Hh + d];
        float a11 = xg[G4 + 1 * Hh + d];
        float a12 = xg[G4 + 2 * Hh + d];
        float a13 = xg[G4 + 3 * Hh + d];
#pragma unroll 4
        for (int k = 0; k < Hh; k++) {
            float4 w = __ldg(&W[k * Hh + d]);
            float h0 = h_sh[cur][0][k];
            float h1 = h_sh[cur][1][k];
            a00 = fmaf(h0, w.x, a00);
            a01 = fmaf(h0, w.y, a01);
            a02 = fmaf(h0, w.z, a02);
            a03 = fmaf(h0, w.w, a03);
            a10 = fmaf(h1, w.x, a10);
            a11 = fmaf(h1, w.y, a11);
            a12 = fmaf(h1, w.z, a12);
            a13 = fmaf(h1, w.w, a13);
        }
        int nxt = cur ^ 1;
        {
            float ig = sigmoidf_(a00), fg = sigmoidf_(a01);
            float gg = tanhf(a02),     og = sigmoidf_(a03);
            float c = fg * c_reg0 + ig * gg;
            float h = og * tanhf(c);
            c_reg0 = c;
            h_sh[nxt][0][d] = h;
            g_enc[((size_t)(b0 + 0) * Ssz + s) * GD + dir * Hh + d] = h;
        }
        {
            float ig = sigmoidf_(a10), fg = sigmoidf_(a11);
            float gg = tanhf(a12),     og = sigmoidf_(a13);
            float c = fg * c_reg1 + ig * gg;
            float h = og * tanhf(c);
            c_reg1 = c;
            h_sh[nxt][1][d] = h;
            g_enc[((size_t)(b0 + 1) * Ssz + s) * GD + dir * Hh + d] = h;
        }
        __syncthreads();
        cur = nxt;
    }
}

// ---------------- 5. masked cumsum over sequence ----------------
__global__ void cumsum_kernel(const int* __restrict__ mask)
{
    int tid = blockIdx.x * blockDim.x + threadIdx.x; // B*GD = 4096
    if (tid >= Bsz * GD) return;
    int b = tid / GD, d = tid % GD;
    float acc = 0.f;
    g_cs[(size_t)b * (Ssz + 1) * GD + d] = 0.f;
#pragma unroll 4
    for (int s = 0; s < Ssz; s++) {
        float v = mask[b * Ssz + s] ? g_enc[((size_t)b * Ssz + s) * GD + d] : 0.f;
        acc += v;
        g_cs[((size_t)b * (Ssz + 1) + s + 1) * GD + d] = acc;
    }
}

// ---------------- 6. span means -> graph_fea (feat[...,0:256]) ----------------
__global__ void span_kernel(const int* __restrict__ ginfo,
                            const int* __restrict__ gnum)
{
    int bn = blockIdx.x;           // b*N + n
    int d = threadIdx.x;           // 0..255
    int b = bn / Nn, n = bn % Nn;
    int st = ginfo[bn * 4 + 0];
    int en = ginfo[bn * 4 + 1];
    bool nm = n < gnum[b];
    float len = (float)max(en - st, 1);
    float v = 0.f;
    if (nm) {
        float a = g_cs[((size_t)b * (Ssz + 1) + en) * GD + d];
        float c = g_cs[((size_t)b * (Ssz + 1) + st) * GD + d];
        v = (a - c) / len;
    }
    g_feat[(size_t)bn * BANK + d] = v;
}

// ---------------- 7. adjacency normalization ----------------
__global__ void adj_kernel(const int* __restrict__ adj,
                           const int* __restrict__ gnum)
{
    int bm = blockIdx.x;           // b*N + m
    int n = threadIdx.x;           // 0..127
    int b = bm / Nn, m = bm % Nn;
    int num = gnum[b];
    bool nm_m = m < num, nm_n = n < num;
    float a = (adj[(size_t)bm * Nn + n] > 0 && nm_m && nm_n) ? 1.f : 0.f;
    __shared__ float red[Nn];
    red[n] = a;
    __syncthreads();
    for (int off = 64; off > 0; off >>= 1) {
        if (n < off) red[n] += red[n + off];
        __syncthreads();
    }
    float denom = fmaxf(red[0], 1.f);
    g_Anorm[(size_t)bm * Nn + n] = a / denom;
}

// ---------------- 8. GCN aggregate: tmp[b,m,:] = Anorm[b,m,:] @ feat[b,:,off:off+256] ----------------
__global__ void gcn_agg_kernel(int off)
{
    int bm = blockIdx.x;
    int d = threadIdx.x;           // 0..255
    int b = bm / Nn;
    __shared__ float arow[Nn];
    if (d < Nn) arow[d] = g_Anorm[(size_t)bm * Nn + d];
    __syncthreads();
    float acc = 0.f;
    const float* base = g_feat + (size_t)b * Nn * BANK + off + d;
#pragma unroll 4
    for (int n = 0; n < Nn; n++)
        acc = fmaf(arow[n], base[(size_t)n * BANK], acc);
    g_tmp[(size_t)bm * GD + d] = acc;
}

// ---------------- 9. entity bank: mean of mention nodes ----------------
__global__ void bank_kernel(const int* __restrict__ ginfo,
                            const int* __restrict__ gnum)
{
    int be = blockIdx.x;           // b*E + e
    int t = threadIdx.x;           // 0..255
    int b = be / Ee, e = be % Ee;
    __shared__ float w[Nn];
    __shared__ float inv;
    if (t < Nn) {
        int base = (b * Nn + t) * 4;
        bool sel = (ginfo[base + 2] == e) && (ginfo[base + 3] == 2) && (t < gnum[b]);
        w[t] = sel ? 1.f : 0.f;
    }
    __syncthreads();
    if (t == 0) {
        float s = 0.f;
        for (int n = 0; n < Nn; n++) s += w[n];
        inv = 1.f / fmaxf(s, 1.f);
    }
    __syncthreads();
#pragma unroll
    for (int u = 0; u < 3; u++) {
        int d = t + u * 256;
        float acc = 0.f;
        const float* base = g_feat + (size_t)b * Nn * BANK + d;
        for (int n = 0; n < Nn; n++)
            acc = fmaf(w[n], base[(size_t)n * BANK], acc);
        g_bank[(size_t)be * BANK + d] = acc * inv;
    }
}

// ---------------- 10. build rel = [h_ent | t_ent | dis_embed] ----------------
__global__ void rel_kernel(const int* __restrict__ pairs,
                           const int* __restrict__ dist,
                           const float* __restrict__ dtab)
{
    size_t idx = (size_t)blockIdx.x * blockDim.x + threadIdx.x;
    size_t total = (size_t)Bsz * Pp * CLSZ;
    if (idx >= total) return;
    int c = (int)(idx % CLSZ);
    int bp = (int)(idx / CLSZ);
    int b = bp / Pp;
    float v;
    if (c < BANK) {
        int hp = pairs[(size_t)bp * 2 + 0];
        v = g_bank[((size_t)b * Ee + hp) * BANK + c];
    } else if (c < 2 * BANK) {
        int tp = pairs[(size_t)bp * 2 + 1];
        v = g_bank[((size_t)b * Ee + tp) * BANK + (c - BANK)];
    } else {
        v = dtab[dist[bp] * 20 + (c - 2 * BANK)];
    }
    g_rel[idx] = v;
}

// ---------------- host launch ----------------
static float* symaddr_cached(const void* sym, float** cache)
{
    if (!*cache) {
        void* p = nullptr;
        cudaGetSymbolAddress(&p, sym);
        *cache = (float*)p;
    }
    return *cache;
}

extern "C" void kernel_launch(void* const* d_in, const int* in_sizes, int n_in,
                              void* d_out, int out_size)
{
    const int*   words   = (const int*)d_in[0];
    const int*   mask    = (const int*)d_in[1];
    const int*   etype   = (const int*)d_in[2];
    const int*   eid     = (const int*)d_in[3];
    // d_in[4] = src_lengths (mask already encodes it)
    const int*   adj     = (const int*)d_in[5];
    const int*   ginfo   = (const int*)d_in[6];
    const int*   gnum    = (const int*)d_in[7];
    const int*   pairs   = (const int*)d_in[8];
    const int*   dist    = (const int*)d_in[9];
    const float* wtab    = (const float*)d_in[10];
    const float* ttab    = (const float*)d_in[11];
    const float* itab    = (const float*)d_in[12];
    const float* Wih_f   = (const float*)d_in[13];
    const float* Whh_f   = (const float*)d_in[14];
    const float* b_f     = (const float*)d_in[15];
    const float* Wih_b   = (const float*)d_in[16];
    const float* Whh_b   = (const float*)d_in[17];
    const float* b_b     = (const float*)d_in[18];
    const float* gcn_W1  = (const float*)d_in[19];
    const float* gcn_b1  = (const float*)d_in[20];
    const float* gcn_W2  = (const float*)d_in[21];
    const float* gcn_b2  = (const float*)d_in[22];
    const float* dtab    = (const float*)d_in[23];
    const float* pW1     = (const float*)d_in[24];
    const float* pb1     = (const float*)d_in[25];
    const float* pW2     = (const float*)d_in[26];
    const float* pb2     = (const float*)d_in[27];
    float* out = (float*)d_out;

    static float *cX = nullptr, *cXG = nullptr, *cFeat = nullptr,
                 *cTmp = nullptr, *cRel = nullptr, *cHid = nullptr;
    float* pX    = symaddr_cached(g_X, &cX);
    float* pXG   = symaddr_cached(g_XG, &cXG);
    float* pFeat = symaddr_cached(g_feat, &cFeat);
    float* pTmp  = symaddr_cached(g_tmp, &cTmp);
    float* pRel  = symaddr_cached(g_rel, &cRel);
    float* pHid  = symaddr_cached(g_hid, &cHid);

    // 1. embeddings
    {
        int total = Ssz * Bsz * INs;
        embed_kernel<<<(total + 255) / 256, 256>>>(words, etype, eid, wtab, ttab, itab);
    }
    // 2. x-gates: XG[dir] = X @ Wih^T + b   (M=8192, N=512, K=140)
    {
        dim3 grid((G4 + BN - 1) / BN, (Ssz * Bsz + BM - 1) / BM);
        sgemm_kernel<<<grid, 256>>>(pX, INs, Wih_f, b_f, pXG, G4,
                                    Ssz * Bsz, G4, INs, 1, 0);
        sgemm_kernel<<<grid, 256>>>(pX, INs, Wih_b, b_b, pXG + (size_t)Ssz * Bsz * G4, G4,
                                    Ssz * Bsz, G4, INs, 1, 0);
    }
    // 3. Whh gate-interleaved pack
    {
        int total = 2 * Hh * G4;
        pack_whh_kernel<<<(total + 255) / 256, 256>>>(Whh_f, Whh_b);
    }
    // 4. BiLSTM recurrence (8 batch-groups x 2 directions, independent blocks)
    lstm_kernel<<<dim3(Bsz / 2, 2), 128>>>();
    // 5. masked cumsum
    cumsum_kernel<<<(Bsz * GD + 255) / 256, 256>>>(mask);
    // 6. span means -> feat[:, :, 0:256]
    span_kernel<<<Bsz * Nn, GD>>>(ginfo, gnum);
    // 7. adjacency normalization
    adj_kernel<<<Bsz * Nn, Nn>>>(adj, gnum);
    // 8. GCN layer 1: h1 = relu((Anorm @ gfea) @ W1 + b1) -> feat[:, :, 256:512]
    gcn_agg_kernel<<<Bsz * Nn, GD>>>(0);
    {
        dim3 grid((GD + BN - 1) / BN, (Bsz * Nn + BM - 1) / BM);
        sgemm_kernel<<<grid, 256>>>(pTmp, GD, gcn_W1, gcn_b1, pFeat + GD, BANK,
                                    Bsz * Nn, GD, GD, 0, 2);
    }
    //    GCN layer 2: h2 = relu((Anorm @ h1) @ W2 + b2) -> feat[:, :, 512:768]
    gcn_agg_kernel<<<Bsz * Nn, GD>>>(GD);
    {
        dim3 grid((GD + BN - 1) / BN, (Bsz * Nn + BM - 1) / BM);
        sgemm_kernel<<<grid, 256>>>(pTmp, GD, gcn_W2, gcn_b2, pFeat + 2 * GD, BANK,
                                    Bsz * Nn, GD, GD, 0, 2);
    }
    // 9. entity bank
    bank_kernel<<<Bsz * Ee, 256>>>(ginfo, gnum);
    // 10. rel features
    {
        size_t total = (size_t)Bsz * Pp * CLSZ;
        rel_kernel<<<(unsigned)((total + 255) / 256), 256>>>(pairs, dist, dtab);
    }
    // 11. MLP layer 1: hid = tanh(rel @ pW1 + pb1)   (M=8192, N=1536, K=1556)
    {
        dim3 grid((HID + BN - 1) / BN, (Bsz * Pp + BM - 1) / BM);
        sgemm_kernel<<<grid, 256>>>(pRel, CLSZ, pW1, pb1, pHid, HID,
                                    Bsz * Pp, HID, CLSZ, 0, 1);
    }
    // 12. MLP layer 2: scores = hid @ pW2 + pb2      (M=8192, N=97, K=1536)
    {
        dim3 grid((Rr + BN - 1) / BN, (Bsz * Pp + BM - 1) / BM);
        sgemm_kernel<<<grid, 256>>>(pHid, HID, pW2, pb2, out, Rr,
                                    Bsz * Pp, Rr, HID, 0, 0);
    }
}

// round 10
// speedup vs baseline: 1.4768x; 1.4768x over previous
#include <cuda_runtime.h>
#include <cuda_bf16.h>
#include <math.h>

// ---------------- problem constants ----------------
#define Bsz   16
#define Ssz   512
#define DE    100
#define DT    20
#define DI    20
#define INs   140     // DE+DT+DI
#define Hh    128
#define GD    256     // 2*H
#define G4    512     // 4*H
#define Nn    128     // nodes
#define Ee    48      // entities
#define Pp    512     // pairs
#define Rr    97      // relations
#define BANK  768     // GD*(ITERS+1)
#define CLSZ  1556    // BANK*2 + 20
#define HID   1536    // BANK*2

// ---------------- device scratch (static; no allocations allowed) ----------------
__device__ float g_X[Ssz * Bsz * INs];              // [s][b][in]
__device__ float g_XG[2ll * Ssz * Bsz * G4];        // [dir][s][b][4H]  (x@Wih^T + bias)
__device__ float g_W4[2 * Hh * G4];                 // [dir][k][d][gate] packed
__device__ float g_enc[(size_t)Bsz * Ssz * GD];     // [b][s][2H]
__device__ float g_cs[(size_t)Bsz * (Ssz + 1) * GD];// cumsum (masked)
__device__ float g_feat[(size_t)Bsz * Nn * BANK];   // [gfea | h1 | h2]
__device__ float g_Anorm[(size_t)Bsz * Nn * Nn];
__device__ float g_tmp[(size_t)Bsz * Nn * GD];      // GCN aggregate scratch
__device__ float g_bank[(size_t)Bsz * Ee * BANK];
__device__ float g_rel[(size_t)Bsz * Pp * CLSZ];
__device__ float g_hid[(size_t)Bsz * Pp * HID];

__device__ __forceinline__ float sigmoidf_(float x) { return 1.f / (1.f + expf(-x)); }

// ---------------- 1. embedding concat ----------------
__global__ void embed_kernel(const int* __restrict__ words,
                             const int* __restrict__ etype,
                             const int* __restrict__ eid,
                             const float* __restrict__ wtab,
                             const float* __restrict__ ttab,
                             const float* __restrict__ itab)
{
    int idx = blockIdx.x * blockDim.x + threadIdx.x;
    int total = Ssz * Bsz * INs;
    if (idx >= total) return;
    int c = idx % INs;
    int sb = idx / INs;
    int b = sb % Bsz;
    int s = sb / Bsz;
    float v;
    if (c < DE)            v = wtab[(size_t)words[b * Ssz + s] * DE + c];
    else if (c < DE + DT)  v = ttab[etype[b * Ssz + s] * DT + (c - DE)];
    else                   v = itab[eid[b * Ssz + s] * DI + (c - DE - DT)];
    g_X[idx] = v;
}

// ---------------- 2. generic SGEMM: C = act(A(MxK) * B + bias) ----------------
// transB==1: B stored [N,K] (use W^T);  transB==0: B stored [K,N]
// act: 0 none, 1 tanh, 2 relu
// Double-buffered smem, register-staged prefetch, one barrier per K-tile,
// conflict-free 4+4 split fragment mapping, vectorized LDG.128 fetch,
// vectorized STG.128 epilogue.
// NOTE: no min-blocks clause — a 128-reg cap forces accumulator spills
// (measured 7568 -> 10524 us regression); let ptxas take ~140 regs.
#define BM 128
#define BN 128
#define BKs 8
#define SP 132   // smem row stride (pad kills STS conflicts; keeps 16B align)
__global__ __launch_bounds__(256)
void sgemm_kernel(const float* __restrict__ A, int lda,
                  const float* __restrict__ Bm,
                  const float* __restrict__ bias,
                  float* __restrict__ C, int ldc,
                  int M, int Nc, int K, int transB, int act)
{
    __shared__ float As[2][BKs][SP];
    __shared__ float Bs[2][BKs][SP];
    int tid = threadIdx.x;
    int tx = tid & 15, ty = tid >> 4;
    int row0 = blockIdx.y * BM, col0 = blockIdx.x * BN;
    float acc[8][8];
#pragma unroll
    for (int i = 0; i < 8; i++)
#pragma unroll
        for (int j = 0; j < 8; j++) acc[i][j] = 0.f;

    // A-load (and B-load when transB=1): float4 along K
    int ar  = tid >> 1;          // 0..127 tile row
    int ak4 = (tid & 1) * 4;     // 0 or 4
    int gr  = row0 + ar;         // A global row
    int gnr = col0 + ar;         // B global row (transB=1)
    // B-load (transB=0): float4 along N
    int bk  = tid >> 5;          // 0..7  (k within tile)
    int bn4 = (tid & 31) * 4;    // 0..124

    float pa[4], pb[4];

    auto fetch = [&](int k0) {
        // ---- A ----
        if (gr < M && k0 + ak4 + 3 < K) {
            float4 v = *(const float4*)(A + (size_t)gr * lda + k0 + ak4);
            pa[0] = v.x; pa[1] = v.y; pa[2] = v.z; pa[3] = v.w;
        } else {
#pragma unroll
            for (int u = 0; u < 4; u++) {
                int gk = k0 + ak4 + u;
                pa[u] = (gr < M && gk < K) ? A[(size_t)gr * lda + gk] : 0.f;
            }
        }
        // ---- B ----
        if (transB) {
            if (gnr < Nc && k0 + ak4 + 3 < K) {
                float4 v = *(const float4*)(Bm + (size_t)gnr * K + k0 + ak4);
                pb[0] = v.x; pb[1] = v.y; pb[2] = v.z; pb[3] = v.w;
            } else {
#pragma unroll
                for (int u = 0; u < 4; u++) {
                    int gk = k0 + ak4 + u;
                    pb[u] = (gnr < Nc && gk < K) ? Bm[(size_t)gnr * K + gk] : 0.f;
                }
            }
        } else {
            int gk = k0 + bk;
            int gc = col0 + bn4;
            if (gk < K && (Nc & 3) == 0 && gc + 3 < Nc) {
                float4 v = *(const float4*)(Bm + (size_t)gk * Nc + gc);
                pb[0] = v.x; pb[1] = v.y; pb[2] = v.z; pb[3] = v.w;
            } else {
#pragma unroll
                for (int u = 0; u < 4; u++) {
                    int c = gc + u;
                    pb[u] = (gk < K && c < Nc) ? Bm[(size_t)gk * Nc + c] : 0.f;
                }
            }
        }
    };
    auto stage = [&](int buf) {
#pragma unroll
        for (int u = 0; u < 4; u++) As[buf][ak4 + u][ar] = pa[u];
        if (transB) {
#pragma unroll
            for (int u = 0; u < 4; u++) Bs[buf][ak4 + u][ar] = pb[u];
        } else {
            *(float4*)&Bs[buf][bk][bn4] = make_float4(pb[0], pb[1], pb[2], pb[3]);
        }
    };

    // prologue: tile 0 resident in buf 0; tile 1 in-flight in registers
    fetch(0);
    stage(0);
    __syncthreads();
    fetch(BKs);   // predicated-safe past K

    int cur = 0;
    for (int k0 = 0; k0 < K; k0 += BKs) {
#pragma unroll
        for (int kk = 0; kk < BKs; kk++) {
            float4 a0 = *(const float4*)&As[cur][kk][ty * 4];
            float4 a1 = *(const float4*)&As[cur][kk][64 + ty * 4];
            float4 b0 = *(const float4*)&Bs[cur][kk][tx * 4];
            float4 b1 = *(const float4*)&Bs[cur][kk][64 + tx * 4];
            float ra[8] = {a0.x, a0.y, a0.z, a0.w, a1.x, a1.y, a1.z, a1.w};
            float rb[8] = {b0.x, b0.y, b0.z, b0.w, b1.x, b1.y, b1.z, b1.w};
#pragma unroll
            for (int i = 0; i < 8; i++)
#pragma unroll
                for (int j = 0; j < 8; j++)
                    acc[i][j] = fmaf(ra[i], rb[j], acc[i][j]);
        }
        if (k0 + BKs < K) {
            stage(cur ^ 1);        // other buffer; its readers finished before
            __syncthreads();       //   the PREVIOUS barrier
            fetch(k0 + 2 * BKs);   // overlap next-next loads with compute
            cur ^= 1;
        }
    }
    // epilogue: two 4-contiguous column runs per row -> STG.128 when possible
    bool vec_st = ((ldc & 3) == 0);
#pragma unroll
    for (int i = 0; i < 8; i++) {
        int rr = row0 + (i < 4 ? ty * 4 + i : 64 + ty * 4 + i - 4);
        if (rr >= M) continue;
#pragma unroll
        for (int jh = 0; jh < 2; jh++) {
            int cc = col0 + jh * 64 + tx * 4;
            float r[4];
#pragma unroll
            for (int u = 0; u < 4; u++) {
                float v = acc[i][jh * 4 + u] + ((cc + u < Nc) ? bias[cc + u] : 0.f);
                if (act == 1) v = tanhf(v);
                else if (act == 2) v = fmaxf(v, 0.f);
                r[u] = v;
            }
            if (vec_st && cc + 3 < Nc) {
                *(float4*)(C + (size_t)rr * ldc + cc) = make_float4(r[0], r[1], r[2], r[3]);
            } else {
#pragma unroll
                for (int u = 0; u < 4; u++)
                    if (cc + u < Nc) C[(size_t)rr * ldc + cc + u] = r[u];
            }
        }
    }
}

// ---------------- 3. Whh pack: g_W4[dir][k][d][g] = Whh[dir][g*128+d][k] ----------------
__global__ void pack_whh_kernel(const float* __restrict__ Whh_f,
                                const float* __restrict__ Whh_b)
{
    int idx = blockIdx.x * blockDim.x + threadIdx.x; // 2 * 128 * 512
    if (idx >= 2 * Hh * G4) return;
    int g = idx & 3;
    int d = (idx >> 2) & (Hh - 1);
    int k = (idx >> 9) & (Hh - 1);
    int dir = idx >> 16;
    const float* W = dir ? Whh_b : Whh_f;
    g_W4[idx] = W[(size_t)(g * Hh + d) * Hh + k];
}

// ---------------- 4. LSTM recurrence ----------------
// One block per (dir, batch-pair). 128 threads; thread d owns h-dim d
// (all 4 gates) for 2 batches. W is gate-interleaved -> one LDG.128 per k.
__global__ __launch_bounds__(128)
void lstm_kernel()
{
    int dir = blockIdx.y;          // 0 fwd, 1 bwd
    int b0 = blockIdx.x * 2;       // batch group
    int d = threadIdx.x;           // 0..127 (h dim)
    __shared__ float h_sh[2][2][Hh];   // [buf][batch][k]
    float c_reg0 = 0.f, c_reg1 = 0.f;
    h_sh[0][0][d] = 0.f;
    h_sh[0][1][d] = 0.f;
    __syncthreads();

    const float4* __restrict__ W = ((const float4*)g_W4) + (size_t)dir * Hh * Hh;
    int cur = 0;
    for (int t = 0; t < Ssz; t++) {
        int s = dir ? (Ssz - 1 - t) : t;
        const float* __restrict__ xg =
            g_XG + (((size_t)dir * Ssz + s) * Bsz + b0) * G4;
        float a00 = xg[0 * Hh + d];
        float a01 = xg[1 * Hh + d];
        float a02 = xg[2 * Hh + d];
        float a03 = xg[3 * Hh + d];
        float a10 = xg[G4 + 0 * Hh + d];
        float a11 = xg[G4 + 1 * Hh + d];
        float a12 = xg[G4 + 2 * Hh + d];
        float a13 = xg[G4 + 3 * Hh + d];
#pragma unroll 4
        for (int k = 0; k < Hh; k++) {
            float4 w = __ldg(&W[k * Hh + d]);
            float h0 = h_sh[cur][0][k];
            float h1 = h_sh[cur][1][k];
            a00 = fmaf(h0, w.x, a00);
            a01 = fmaf(h0, w.y, a01);
            a02 = fmaf(h0, w.z, a02);
            a03 = fmaf(h0, w.w, a03);
            a10 = fmaf(h1, w.x, a10);
            a11 = fmaf(h1, w.y, a11);
            a12 = fmaf(h1, w.z, a12);
            a13 = fmaf(h1, w.w, a13);
        }
        int nxt = cur ^ 1;
        {
            float ig = sigmoidf_(a00), fg = sigmoidf_(a01);
            float gg = tanhf(a02),     og = sigmoidf_(a03);
            float c = fg * c_reg0 + ig * gg;
            float h = og * tanhf(c);
            c_reg0 = c;
            h_sh[nxt][0][d] = h;
            g_enc[((size_t)(b0 + 0) * Ssz + s) * GD + dir * Hh + d] = h;
        }
        {
            float ig = sigmoidf_(a10), fg = sigmoidf_(a11);
            float gg = tanhf(a12),     og = sigmoidf_(a13);
            float c = fg * c_reg1 + ig * gg;
            float h = og * tanhf(c);
            c_reg1 = c;
            h_sh[nxt][1][d] = h;
            g_enc[((size_t)(b0 + 1) * Ssz + s) * GD + dir * Hh + d] = h;
        }
        __syncthreads();
        cur = nxt;
    }
}

// ---------------- 5. masked cumsum over sequence ----------------
__global__ void cumsum_kernel(const int* __restrict__ mask)
{
    int tid = blockIdx.x * blockDim.x + threadIdx.x; // B*GD = 4096
    if (tid >= Bsz * GD) return;
    int b = tid / GD, d = tid % GD;
    float acc = 0.f;
    g_cs[(size_t)b * (Ssz + 1) * GD + d] = 0.f;
#pragma unroll 4
    for (int s = 0; s < Ssz; s++) {
        float v = mask[b * Ssz + s] ? g_enc[((size_t)b * Ssz + s) * GD + d] : 0.f;
        acc += v;
        g_cs[((size_t)b * (Ssz + 1) + s + 1) * GD + d] = acc;
    }
}

// ---------------- 6. span means -> graph_fea (feat[...,0:256]) ----------------
__global__ void span_kernel(const int* __restrict__ ginfo,
                            const int* __restrict__ gnum)
{
    int bn = blockIdx.x;           // b*N + n
    int d = threadIdx.x;           // 0..255
    int b = bn / Nn, n = bn % Nn;
    int st = ginfo[bn * 4 + 0];
    int en = ginfo[bn * 4 + 1];
    bool nm = n < gnum[b];
    float len = (float)max(en - st, 1);
    float v = 0.f;
    if (nm) {
        float a = g_cs[((size_t)b * (Ssz + 1) + en) * GD + d];
        float c = g_cs[((size_t)b * (Ssz + 1) + st) * GD + d];
        v = (a - c) / len;
    }
    g_feat[(size_t)bn * BANK + d] = v;
}

// ---------------- 7. adjacency normalization ----------------
__global__ void adj_kernel(const int* __restrict__ adj,
                           const int* __restrict__ gnum)
{
    int bm = blockIdx.x;           // b*N + m
    int n = threadIdx.x;           // 0..127
    int b = bm / Nn, m = bm % Nn;
    int num = gnum[b];
    bool nm_m = m < num, nm_n = n < num;
    float a = (adj[(size_t)bm * Nn + n] > 0 && nm_m && nm_n) ? 1.f : 0.f;
    __shared__ float red[Nn];
    red[n] = a;
    __syncthreads();
    for (int off = 64; off > 0; off >>= 1) {
        if (n < off) red[n] += red[n + off];
        __syncthreads();
    }
    float denom = fmaxf(red[0], 1.f);
    g_Anorm[(size_t)bm * Nn + n] = a / denom;
}

// ---------------- 8. GCN aggregate: tmp[b,m,:] = Anorm[b,m,:] @ feat[b,:,off:off+256] ----------------
__global__ void gcn_agg_kernel(int off)
{
    int bm = blockIdx.x;
    int d = threadIdx.x;           // 0..255
    int b = bm / Nn;
    __shared__ float arow[Nn];
    if (d < Nn) arow[d] = g_Anorm[(size_t)bm * Nn + d];
    __syncthreads();
    float acc = 0.f;
    const float* base = g_feat + (size_t)b * Nn * BANK + off + d;
#pragma unroll 4
    for (int n = 0; n < Nn; n++)
        acc = fmaf(arow[n], base[(size_t)n * BANK], acc);
    g_tmp[(size_t)bm * GD + d] = acc;
}

// ---------------- 9. entity bank: mean of mention nodes ----------------
__global__ void bank_kernel(const int* __restrict__ ginfo,
                            const int* __restrict__ gnum)
{
    int be = blockIdx.x;           // b*E + e
    int t = threadIdx.x;           // 0..255
    int b = be / Ee, e = be % Ee;
    __shared__ float w[Nn];
    __shared__ float inv;
    if (t < Nn) {
        int base = (b * Nn + t) * 4;
        bool sel = (ginfo[base + 2] == e) && (ginfo[base + 3] == 2) && (t < gnum[b]);
        w[t] = sel ? 1.f : 0.f;
    }
    __syncthreads();
    if (t == 0) {
        float s = 0.f;
        for (int n = 0; n < Nn; n++) s += w[n];
        inv = 1.f / fmaxf(s, 1.f);
    }
    __syncthreads();
#pragma unroll
    for (int u = 0; u < 3; u++) {
        int d = t + u * 256;
        float acc = 0.f;
        const float* base = g_feat + (size_t)b * Nn * BANK + d;
        for (int n = 0; n < Nn; n++)
            acc = fmaf(w[n], base[(size_t)n * BANK], acc);
        g_bank[(size_t)be * BANK + d] = acc * inv;
    }
}

// ---------------- 10. build rel = [h_ent | t_ent | dis_embed] ----------------
__global__ void rel_kernel(const int* __restrict__ pairs,
                           const int* __restrict__ dist,
                           const float* __restrict__ dtab)
{
    size_t idx = (size_t)blockIdx.x * blockDim.x + threadIdx.x;
    size_t total = (size_t)Bsz * Pp * CLSZ;
    if (idx >= total) return;
    int c = (int)(idx % CLSZ);
    int bp = (int)(idx / CLSZ);
    int b = bp / Pp;
    float v;
    if (c < BANK) {
        int hp = pairs[(size_t)bp * 2 + 0];
        v = g_bank[((size_t)b * Ee + hp) * BANK + c];
    } else if (c < 2 * BANK) {
        int tp = pairs[(size_t)bp * 2 + 1];
        v = g_bank[((size_t)b * Ee + tp) * BANK + (c - BANK)];
    } else {
        v = dtab[dist[bp] * 20 + (c - 2 * BANK)];
    }
    g_rel[idx] = v;
}

// ---------------- host launch ----------------
static float* symaddr_cached(const void* sym, float** cache)
{
    if (!*cache) {
        void* p = nullptr;
        cudaGetSymbolAddress(&p, sym);
        *cache = (float*)p;
    }
    return *cache;
}

extern "C" void kernel_launch(void* const* d_in, const int* in_sizes, int n_in,
                              void* d_out, int out_size)
{
    const int*   words   = (const int*)d_in[0];
    const int*   mask    = (const int*)d_in[1];
    const int*   etype   = (const int*)d_in[2];
    const int*   eid     = (const int*)d_in[3];
    // d_in[4] = src_lengths (mask already encodes it)
    const int*   adj     = (const int*)d_in[5];
    const int*   ginfo   = (const int*)d_in[6];
    const int*   gnum    = (const int*)d_in[7];
    const int*   pairs   = (const int*)d_in[8];
    const int*   dist    = (const int*)d_in[9];
    const float* wtab    = (const float*)d_in[10];
    const float* ttab    = (const float*)d_in[11];
    const float* itab    = (const float*)d_in[12];
    const float* Wih_f   = (const float*)d_in[13];
    const float* Whh_f   = (const float*)d_in[14];
    const float* b_f     = (const float*)d_in[15];
    const float* Wih_b   = (const float*)d_in[16];
    const float* Whh_b   = (const float*)d_in[17];
    const float* b_b     = (const float*)d_in[18];
    const float* gcn_W1  = (const float*)d_in[19];
    const float* gcn_b1  = (const float*)d_in[20];
    const float* gcn_W2  = (const float*)d_in[21];
    const float* gcn_b2  = (const float*)d_in[22];
    const float* dtab    = (const float*)d_in[23];
    const float* pW1     = (const float*)d_in[24];
    const float* pb1     = (const float*)d_in[25];
    const float* pW2     = (const float*)d_in[26];
    const float* pb2     = (const float*)d_in[27];
    float* out = (float*)d_out;

    static float *cX = nullptr, *cXG = nullptr, *cFeat = nullptr,
                 *cTmp = nullptr, *cRel = nullptr, *cHid = nullptr;
    float* pX    = symaddr_cached(g_X, &cX);
    float* pXG   = symaddr_cached(g_XG, &cXG);
    float* pFeat = symaddr_cached(g_feat, &cFeat);
    float* pTmp  = symaddr_cached(g_tmp, &cTmp);
    float* pRel  = symaddr_cached(g_rel, &cRel);
    float* pHid  = symaddr_cached(g_hid, &cHid);

    // 1. embeddings
    {
        int total = Ssz * Bsz * INs;
        embed_kernel<<<(total + 255) / 256, 256>>>(words, etype, eid, wtab, ttab, itab);
    }
    // 2. x-gates: XG[dir] = X @ Wih^T + b   (M=8192, N=512, K=140)
    {
        dim3 grid((G4 + BN - 1) / BN, (Ssz * Bsz + BM - 1) / BM);
        sgemm_kernel<<<grid, 256>>>(pX, INs, Wih_f, b_f, pXG, G4,
                                    Ssz * Bsz, G4, INs, 1, 0);
        sgemm_kernel<<<grid, 256>>>(pX, INs, Wih_b, b_b, pXG + (size_t)Ssz * Bsz * G4, G4,
                                    Ssz * Bsz, G4, INs, 1, 0);
    }
    // 3. Whh gate-interleaved pack
    {
        int total = 2 * Hh * G4;
        pack_whh_kernel<<<(total + 255) / 256, 256>>>(Whh_f, Whh_b);
    }
    // 4. BiLSTM recurrence (8 batch-groups x 2 directions, independent blocks)
    lstm_kernel<<<dim3(Bsz / 2, 2), 128>>>();
    // 5. masked cumsum
    cumsum_kernel<<<(Bsz * GD + 255) / 256, 256>>>(mask);
    // 6. span means -> feat[:, :, 0:256]
    span_kernel<<<Bsz * Nn, GD>>>(ginfo, gnum);
    // 7. adjacency normalization
    adj_kernel<<<Bsz * Nn, Nn>>>(adj, gnum);
    // 8. GCN layer 1: h1 = relu((Anorm @ gfea) @ W1 + b1) -> feat[:, :, 256:512]
    gcn_agg_kernel<<<Bsz * Nn, GD>>>(0);
    {
        dim3 grid((GD + BN - 1) / BN, (Bsz * Nn + BM - 1) / BM);
        sgemm_kernel<<<grid, 256>>>(pTmp, GD, gcn_W1, gcn_b1, pFeat + GD, BANK,
                                    Bsz * Nn, GD, GD, 0, 2);
    }
    //    GCN layer 2: h2 = relu((Anorm @ h1) @ W2 + b2) -> feat[:, :, 512:768]
    gcn_agg_kernel<<<Bsz * Nn, GD>>>(GD);
    {
        dim3 grid((GD + BN - 1) / BN, (Bsz * Nn + BM - 1) / BM);
        sgemm_kernel<<<grid, 256>>>(pTmp, GD, gcn_W2, gcn_b2, pFeat + 2 * GD, BANK,
                                    Bsz * Nn, GD, GD, 0, 2);
    }
    // 9. entity bank
    bank_kernel<<<Bsz * Ee, 256>>>(ginfo, gnum);
    // 10. rel features
    {
        size_t total = (size_t)Bsz * Pp * CLSZ;
        rel_kernel<<<(unsigned)((total + 255) / 256), 256>>>(pairs, dist, dtab);
    }
    // 11. MLP layer 1: hid = tanh(rel @ pW1 + pb1)   (M=8192, N=1536, K=1556)
    {
        dim3 grid((HID + BN - 1) / BN, (Bsz * Pp + BM - 1) / BM);
        sgemm_kernel<<<grid, 256>>>(pRel, CLSZ, pW1, pb1, pHid, HID,
                                    Bsz * Pp, HID, CLSZ, 0, 1);
    }
    // 12. MLP layer 2: scores = hid @ pW2 + pb2      (M=8192, N=97, K=1536)
    {
        dim3 grid((Rr + BN - 1) / BN, (Bsz * Pp + BM - 1) / BM);
        sgemm_kernel<<<grid, 256>>>(pHid, HID, pW2, pb2, out, Rr,
                                    Bsz * Pp, Rr, HID, 0, 0);
    }
}

// round 12
// speedup vs baseline: 3.5646x; 2.4136x over previous
#include <cuda_runtime.h>
#include <cuda_bf16.h>
#include <math.h>

// ---------------- problem constants ----------------
#define Bsz   16
#define Ssz   512
#define DE    100
#define DT    20
#define DI    20
#define INs   140     // DE+DT+DI
#define Hh    128
#define GD    256     // 2*H
#define G4    512     // 4*H
#define Nn    128     // nodes
#define Ee    48      // entities
#define Pp    512     // pairs
#define Rr    97      // relations
#define BANK  768     // GD*(ITERS+1)
#define CLSZ  1556    // BANK*2 + 20
#define HID   1536    // BANK*2

// ---------------- device scratch (static; no allocations allowed) ----------------
__device__ float g_X[Ssz * Bsz * INs];              // [s][b][in]
__device__ float g_XG[2ll * Ssz * Bsz * G4];        // [dir][s][b][4H]  (x@Wih^T + bias)
__device__ float g_W4[2 * Hh * G4];                 // [dir][k][d][gate] packed
__device__ float g_enc[(size_t)Bsz * Ssz * GD];     // [b][s][2H]
__device__ float g_cs[(size_t)Bsz * (Ssz + 1) * GD];// cumsum (masked)
__device__ float g_feat[(size_t)Bsz * Nn * BANK];   // [gfea | h1 | h2]
__device__ float g_Anorm[(size_t)Bsz * Nn * Nn];
__device__ float g_tmp[(size_t)Bsz * Nn * GD];      // GCN aggregate scratch
__device__ float g_bank[(size_t)Bsz * Ee * BANK];
__device__ float g_rel[(size_t)Bsz * Pp * CLSZ];
__device__ float g_hid[(size_t)Bsz * Pp * HID];

__device__ __forceinline__ float sigmoidf_(float x) { return 1.f / (1.f + expf(-x)); }

// ---------------- 1. embedding concat ----------------
__global__ void embed_kernel(const int* __restrict__ words,
                             const int* __restrict__ etype,
                             const int* __restrict__ eid,
                             const float* __restrict__ wtab,
                             const float* __restrict__ ttab,
                             const float* __restrict__ itab)
{
    int idx = blockIdx.x * blockDim.x + threadIdx.x;
    int total = Ssz * Bsz * INs;
    if (idx >= total) return;
    int c = idx % INs;
    int sb = idx / INs;
    int b = sb % Bsz;
    int s = sb / Bsz;
    float v;
    if (c < DE)            v = wtab[(size_t)words[b * Ssz + s] * DE + c];
    else if (c < DE + DT)  v = ttab[etype[b * Ssz + s] * DT + (c - DE)];
    else                   v = itab[eid[b * Ssz + s] * DI + (c - DE - DT)];
    g_X[idx] = v;
}

// ---------------- 2. generic SGEMM: C = act(A(MxK) * B + bias) ----------------
// transB==1: B stored [N,K] (use W^T);  transB==0: B stored [K,N]
// act: 0 none, 1 tanh, 2 relu
// Double-buffered smem, register-staged prefetch, one barrier per K-tile,
// conflict-free 4+4 split fragment mapping, vectorized LDG.128 fetch,
// vectorized STG.128 epilogue.
// NOTE: no min-blocks clause — a 128-reg cap forces accumulator spills
// (measured 7568 -> 10524 us regression); let ptxas take ~140 regs.
#define BM 128
#define BN 128
#define BKs 8
#define SP 132   // smem row stride (pad kills STS conflicts; keeps 16B align)
__global__ __launch_bounds__(256)
void sgemm_kernel(const float* __restrict__ A, int lda,
                  const float* __restrict__ Bm,
                  const float* __restrict__ bias,
                  float* __restrict__ C, int ldc,
                  int M, int Nc, int K, int transB, int act)
{
    __shared__ float As[2][BKs][SP];
    __shared__ float Bs[2][BKs][SP];
    int tid = threadIdx.x;
    int tx = tid & 15, ty = tid >> 4;
    int row0 = blockIdx.y * BM, col0 = blockIdx.x * BN;
    float acc[8][8];
#pragma unroll
    for (int i = 0; i < 8; i++)
#pragma unroll
        for (int j = 0; j < 8; j++) acc[i][j] = 0.f;

    // A-load (and B-load when transB=1): float4 along K
    int ar  = tid >> 1;          // 0..127 tile row
    int ak4 = (tid & 1) * 4;     // 0 or 4
    int gr  = row0 + ar;         // A global row
    int gnr = col0 + ar;         // B global row (transB=1)
    // B-load (transB=0): float4 along N
    int bk  = tid >> 5;          // 0..7  (k within tile)
    int bn4 = (tid & 31) * 4;    // 0..124

    float pa[4], pb[4];

    auto fetch = [&](int k0) {
        // ---- A ----
        if (gr < M && k0 + ak4 + 3 < K) {
            float4 v = *(const float4*)(A + (size_t)gr * lda + k0 + ak4);
            pa[0] = v.x; pa[1] = v.y; pa[2] = v.z; pa[3] = v.w;
        } else {
#pragma unroll
            for (int u = 0; u < 4; u++) {
                int gk = k0 + ak4 + u;
                pa[u] = (gr < M && gk < K) ? A[(size_t)gr * lda + gk] : 0.f;
            }
        }
        // ---- B ----
        if (transB) {
            if (gnr < Nc && k0 + ak4 + 3 < K) {
                float4 v = *(const float4*)(Bm + (size_t)gnr * K + k0 + ak4);
                pb[0] = v.x; pb[1] = v.y; pb[2] = v.z; pb[3] = v.w;
            } else {
#pragma unroll
                for (int u = 0; u < 4; u++) {
                    int gk = k0 + ak4 + u;
                    pb[u] = (gnr < Nc && gk < K) ? Bm[(size_t)gnr * K + gk] : 0.f;
                }
            }
        } else {
            int gk = k0 + bk;
            int gc = col0 + bn4;
            if (gk < K && (Nc & 3) == 0 && gc + 3 < Nc) {
                float4 v = *(const float4*)(Bm + (size_t)gk * Nc + gc);
                pb[0] = v.x; pb[1] = v.y; pb[2] = v.z; pb[3] = v.w;
            } else {
#pragma unroll
                for (int u = 0; u < 4; u++) {
                    int c = gc + u;
                    pb[u] = (gk < K && c < Nc) ? Bm[(size_t)gk * Nc + c] : 0.f;
                }
            }
        }
    };
    auto stage = [&](int buf) {
#pragma unroll
        for (int u = 0; u < 4; u++) As[buf][ak4 + u][ar] = pa[u];
        if (transB) {
#pragma unroll
            for (int u = 0; u < 4; u++) Bs[buf][ak4 + u][ar] = pb[u];
        } else {
            *(float4*)&Bs[buf][bk][bn4] = make_float4(pb[0], pb[1], pb[2], pb[3]);
        }
    };

    // prologue: tile 0 resident in buf 0; tile 1 in-flight in registers
    fetch(0);
    stage(0);
    __syncthreads();
    fetch(BKs);   // predicated-safe past K

    int cur = 0;
    for (int k0 = 0; k0 < K; k0 += BKs) {
#pragma unroll
        for (int kk = 0; kk < BKs; kk++) {
            float4 a0 = *(const float4*)&As[cur][kk][ty * 4];
            float4 a1 = *(const float4*)&As[cur][kk][64 + ty * 4];
            float4 b0 = *(const float4*)&Bs[cur][kk][tx * 4];
            float4 b1 = *(const float4*)&Bs[cur][kk][64 + tx * 4];
            float ra[8] = {a0.x, a0.y, a0.z, a0.w, a1.x, a1.y, a1.z, a1.w};
            float rb[8] = {b0.x, b0.y, b0.z, b0.w, b1.x, b1.y, b1.z, b1.w};
#pragma unroll
            for (int i = 0; i < 8; i++)
#pragma unroll
                for (int j = 0; j < 8; j++)
                    acc[i][j] = fmaf(ra[i], rb[j], acc[i][j]);
        }
        if (k0 + BKs < K) {
            stage(cur ^ 1);        // other buffer; its readers finished before
            __syncthreads();       //   the PREVIOUS barrier
            fetch(k0 + 2 * BKs);   // overlap next-next loads with compute
            cur ^= 1;
        }
    }
    // epilogue: two 4-contiguous column runs per row -> STG.128 when possible
    bool vec_st = ((ldc & 3) == 0);
#pragma unroll
    for (int i = 0; i < 8; i++) {
        int rr = row0 + (i < 4 ? ty * 4 + i : 64 + ty * 4 + i - 4);
        if (rr >= M) continue;
#pragma unroll
        for (int jh = 0; jh < 2; jh++) {
            int cc = col0 + jh * 64 + tx * 4;
            float r[4];
#pragma unroll
            for (int u = 0; u < 4; u++) {
                float v = acc[i][jh * 4 + u] + ((cc + u < Nc) ? bias[cc + u] : 0.f);
                if (act == 1) v = tanhf(v);
                else if (act == 2) v = fmaxf(v, 0.f);
                r[u] = v;
            }
            if (vec_st && cc + 3 < Nc) {
                *(float4*)(C + (size_t)rr * ldc + cc) = make_float4(r[0], r[1], r[2], r[3]);
            } else {
#pragma unroll
                for (int u = 0; u < 4; u++)
                    if (cc + u < Nc) C[(size_t)rr * ldc + cc + u] = r[u];
            }
        }
    }
}

// ---------------- 3. Whh pack: g_W4[dir][k][d][g] = Whh[dir][g*128+d][k] ----------------
__global__ void pack_whh_kernel(const float* __restrict__ Whh_f,
                                const float* __restrict__ Whh_b)
{
    int idx = blockIdx.x * blockDim.x + threadIdx.x; // 2 * 128 * 512
    if (idx >= 2 * Hh * G4) return;
    int g = idx & 3;
    int d = (idx >> 2) & (Hh - 1);
    int k = (idx >> 9) & (Hh - 1);
    int dir = idx >> 16;
    const float* W = dir ? Whh_b : Whh_f;
    g_W4[idx] = W[(size_t)(g * Hh + d) * Hh + k];
}

// ---------------- 4. LSTM recurrence ----------------
// One block per (dir, batch-pair). 128 threads; thread d owns h-dim d
// (all 4 gates) for 2 batches. W is gate-interleaved -> one LDG.128 per k.
// W (256KB/dir) exceeds L1 (228KB) -> every step streams from L2 (~250cyc).
// Double-buffered 16-deep W prefetch (wv[2][16]) hides that latency; the
// last chunk prefetches chunk 0 for the NEXT timestep (W is step-invariant),
// so the load pipeline never drains. The chunk loop is FULLY UNROLLED so the
// ping-pong index pc is compile-time constant and wv stays in registers
// (dynamic indexing would demote it to local memory). FMA order stays k
// ascending (bit-identical numerics).
__global__ __launch_bounds__(128)
void lstm_kernel()
{
    int dir = blockIdx.y;          // 0 fwd, 1 bwd
    int b0 = blockIdx.x * 2;       // batch group
    int d = threadIdx.x;           // 0..127 (h dim)
    __shared__ float h_sh[2][2][Hh];   // [buf][batch][k]
    float c_reg0 = 0.f, c_reg1 = 0.f;
    h_sh[0][0][d] = 0.f;
    h_sh[0][1][d] = 0.f;
    __syncthreads();

    const float4* __restrict__ W = ((const float4*)g_W4) + (size_t)dir * Hh * Hh;

    float4 wv[2][16];
#pragma unroll
    for (int u = 0; u < 16; u++) wv[0][u] = __ldg(&W[u * Hh + d]);

    int cur = 0;
    for (int t = 0; t < Ssz; t++) {
        int s = dir ? (Ssz - 1 - t) : t;
        const float* __restrict__ xg =
            g_XG + (((size_t)dir * Ssz + s) * Bsz + b0) * G4;
        float a00 = xg[0 * Hh + d];
        float a01 = xg[1 * Hh + d];
        float a02 = xg[2 * Hh + d];
        float a03 = xg[3 * Hh + d];
        float a10 = xg[G4 + 0 * Hh + d];
        float a11 = xg[G4 + 1 * Hh + d];
        float a12 = xg[G4 + 2 * Hh + d];
        float a13 = xg[G4 + 3 * Hh + d];

        // 8 chunks of 16; FULL unroll -> pc = kcN&1 is compile-time, wv stays
        // in registers. pc returns to 0 after 8 flips (cross-step consistent).
#pragma unroll
        for (int kcN = 0; kcN < Hh / 16; kcN++) {
            const int kc = kcN * 16;
            const int pc = kcN & 1;
            const int nc = pc ^ 1;
            const int kn = (kc + 16) & (Hh - 1);   // wraps to 0 on last chunk
#pragma unroll
            for (int u = 0; u < 16; u++)
                wv[nc][u] = __ldg(&W[(kn + u) * Hh + d]);
#pragma unroll
            for (int u = 0; u < 16; u++) {
                float4 w = wv[pc][u];
                float h0 = h_sh[cur][0][kc + u];
                float h1 = h_sh[cur][1][kc + u];
                a00 = fmaf(h0, w.x, a00);
                a01 = fmaf(h0, w.y, a01);
                a02 = fmaf(h0, w.z, a02);
                a03 = fmaf(h0, w.w, a03);
                a10 = fmaf(h1, w.x, a10);
                a11 = fmaf(h1, w.y, a11);
                a12 = fmaf(h1, w.z, a12);
                a13 = fmaf(h1, w.w, a13);
            }
        }
        int nxt = cur ^ 1;
        {
            float ig = sigmoidf_(a00), fg = sigmoidf_(a01);
            float gg = tanhf(a02),     og = sigmoidf_(a03);
            float c = fg * c_reg0 + ig * gg;
            float h = og * tanhf(c);
            c_reg0 = c;
            h_sh[nxt][0][d] = h;
            g_enc[((size_t)(b0 + 0) * Ssz + s) * GD + dir * Hh + d] = h;
        }
        {
            float ig = sigmoidf_(a10), fg = sigmoidf_(a11);
            float gg = tanhf(a12),     og = sigmoidf_(a13);
            float c = fg * c_reg1 + ig * gg;
            float h = og * tanhf(c);
            c_reg1 = c;
            h_sh[nxt][1][d] = h;
            g_enc[((size_t)(b0 + 1) * Ssz + s) * GD + dir * Hh + d] = h;
        }
        __syncthreads();
        cur = nxt;
    }
}

// ---------------- 5. masked cumsum over sequence ----------------
__global__ void cumsum_kernel(const int* __restrict__ mask)
{
    int tid = blockIdx.x * blockDim.x + threadIdx.x; // B*GD = 4096
    if (tid >= Bsz * GD) return;
    int b = tid / GD, d = tid % GD;
    float acc = 0.f;
    g_cs[(size_t)b * (Ssz + 1) * GD + d] = 0.f;
#pragma unroll 4
    for (int s = 0; s < Ssz; s++) {
        float v = mask[b * Ssz + s] ? g_enc[((size_t)b * Ssz + s) * GD + d] : 0.f;
        acc += v;
        g_cs[((size_t)b * (Ssz + 1) + s + 1) * GD + d] = acc;
    }
}

// ---------------- 6. span means -> graph_fea (feat[...,0:256]) ----------------
__global__ void span_kernel(const int* __restrict__ ginfo,
                            const int* __restrict__ gnum)
{
    int bn = blockIdx.x;           // b*N + n
    int d = threadIdx.x;           // 0..255
    int b = bn / Nn, n = bn % Nn;
    int st = ginfo[bn * 4 + 0];
    int en = ginfo[bn * 4 + 1];
    bool nm = n < gnum[b];
    float len = (float)max(en - st, 1);
    float v = 0.f;
    if (nm) {
        float a = g_cs[((size_t)b * (Ssz + 1) + en) * GD + d];
        float c = g_cs[((size_t)b * (Ssz + 1) + st) * GD + d];
        v = (a - c) / len;
    }
    g_feat[(size_t)bn * BANK + d] = v;
}

// ---------------- 7. adjacency normalization ----------------
__global__ void adj_kernel(const int* __restrict__ adj,
                           const int* __restrict__ gnum)
{
    int bm = blockIdx.x;           // b*N + m
    int n = threadIdx.x;           // 0..127
    int b = bm / Nn, m = bm % Nn;
    int num = gnum[b];
    bool nm_m = m < num, nm_n = n < num;
    float a = (adj[(size_t)bm * Nn + n] > 0 && nm_m && nm_n) ? 1.f : 0.f;
    __shared__ float red[Nn];
    red[n] = a;
    __syncthreads();
    for (int off = 64; off > 0; off >>= 1) {
        if (n < off) red[n] += red[n + off];
        __syncthreads();
    }
    float denom = fmaxf(red[0], 1.f);
    g_Anorm[(size_t)bm * Nn + n] = a / denom;
}

// ---------------- 8. GCN aggregate: tmp[b,m,:] = Anorm[b,m,:] @ feat[b,:,off:off+256] ----------------
__global__ void gcn_agg_kernel(int off)
{
    int bm = blockIdx.x;
    int d = threadIdx.x;           // 0..255
    int b = bm / Nn;
    __shared__ float arow[Nn];
    if (d < Nn) arow[d] = g_Anorm[(size_t)bm * Nn + d];
    __syncthreads();
    float acc = 0.f;
    const float* base = g_feat + (size_t)b * Nn * BANK + off + d;
#pragma unroll 4
    for (int n = 0; n < Nn; n++)
        acc = fmaf(arow[n], base[(size_t)n * BANK], acc);
    g_tmp[(size_t)bm * GD + d] = acc;
}

// ---------------- 9. entity bank: mean of mention nodes ----------------
__global__ void bank_kernel(const int* __restrict__ ginfo,
                            const int* __restrict__ gnum)
{
    int be = blockIdx.x;           // b*E + e
    int t = threadIdx.x;           // 0..255
    int b = be / Ee, e = be % Ee;
    __shared__ float w[Nn];
    __shared__ float inv;
    if (t < Nn) {
        int base = (b * Nn + t) * 4;
        bool sel = (ginfo[base + 2] == e) && (ginfo[base + 3] == 2) && (t < gnum[b]);
        w[t] = sel ? 1.f : 0.f;
    }
    __syncthreads();
    if (t == 0) {
        float s = 0.f;
        for (int n = 0; n < Nn; n++) s += w[n];
        inv = 1.f / fmaxf(s, 1.f);
    }
    __syncthreads();
#pragma unroll
    for (int u = 0; u < 3; u++) {
        int d = t + u * 256;
        float acc = 0.f;
        const float* base = g_feat + (size_t)b * Nn * BANK + d;
        for (int n = 0; n < Nn; n++)
            acc = fmaf(w[n], base[(size_t)n * BANK], acc);
        g_bank[(size_t)be * BANK + d] = acc * inv;
    }
}

// ---------------- 10. build rel = [h_ent | t_ent | dis_embed] ----------------
__global__ void rel_kernel(const int* __restrict__ pairs,
                           const int* __restrict__ dist,
                           const float* __restrict__ dtab)
{
    size_t idx = (size_t)blockIdx.x * blockDim.x + threadIdx.x;
    size_t total = (size_t)Bsz * Pp * CLSZ;
    if (idx >= total) return;
    int c = (int)(idx % CLSZ);
    int bp = (int)(idx / CLSZ);
    int b = bp / Pp;
    float v;
    if (c < BANK) {
        int hp = pairs[(size_t)bp * 2 + 0];
        v = g_bank[((size_t)b * Ee + hp) * BANK + c];
    } else if (c < 2 * BANK) {
        int tp = pairs[(size_t)bp * 2 + 1];
        v = g_bank[((size_t)b * Ee + tp) * BANK + (c - BANK)];
    } else {
        v = dtab[dist[bp] * 20 + (c - 2 * BANK)];
    }
    g_rel[idx] = v;
}

// ---------------- host launch ----------------
static float* symaddr_cached(const void* sym, float** cache)
{
    if (!*cache) {
        void* p = nullptr;
        cudaGetSymbolAddress(&p, sym);
        *cache = (float*)p;
    }
    return *cache;
}

extern "C" void kernel_launch(void* const* d_in, const int* in_sizes, int n_in,
                              void* d_out, int out_size)
{
    const int*   words   = (const int*)d_in[0];
    const int*   mask    = (const int*)d_in[1];
    const int*   etype   = (const int*)d_in[2];
    const int*   eid     = (const int*)d_in[3];
    // d_in[4] = src_lengths (mask already encodes it)
    const int*   adj     = (const int*)d_in[5];
    const int*   ginfo   = (const int*)d_in[6];
    const int*   gnum    = (const int*)d_in[7];
    const int*   pairs   = (const int*)d_in[8];
    const int*   dist    = (const int*)d_in[9];
    const float* wtab    = (const float*)d_in[10];
    const float* ttab    = (const float*)d_in[11];
    const float* itab    = (const float*)d_in[12];
    const float* Wih_f   = (const float*)d_in[13];
    const float* Whh_f   = (const float*)d_in[14];
    const float* b_f     = (const float*)d_in[15];
    const float* Wih_b   = (const float*)d_in[16];
    const float* Whh_b   = (const float*)d_in[17];
    const float* b_b     = (const float*)d_in[18];
    const float* gcn_W1  = (const float*)d_in[19];
    const float* gcn_b1  = (const float*)d_in[20];
    const float* gcn_W2  = (const float*)d_in[21];
    const float* gcn_b2  = (const float*)d_in[22];
    const float* dtab    = (const float*)d_in[23];
    const float* pW1     = (const float*)d_in[24];
    const float* pb1     = (const float*)d_in[25];
    const float* pW2     = (const float*)d_in[26];
    const float* pb2     = (const float*)d_in[27];
    float* out = (float*)d_out;

    static float *cX = nullptr, *cXG = nullptr, *cFeat = nullptr,
                 *cTmp = nullptr, *cRel = nullptr, *cHid = nullptr;
    float* pX    = symaddr_cached(g_X, &cX);
    float* pXG   = symaddr_cached(g_XG, &cXG);
    float* pFeat = symaddr_cached(g_feat, &cFeat);
    float* pTmp  = symaddr_cached(g_tmp, &cTmp);
    float* pRel  = symaddr_cached(g_rel, &cRel);
    float* pHid  = symaddr_cached(g_hid, &cHid);

    // 0. Whh gate-interleaved pack (no deps — launched FIRST so ncu's fixed
    //    capture slot shifts onto an sgemm launch for diagnosis)
    {
        int total = 2 * Hh * G4;
        pack_whh_kernel<<<(total + 255) / 256, 256>>>(Whh_f, Whh_b);
    }
    // 1. embeddings
    {
        int total = Ssz * Bsz * INs;
        embed_kernel<<<(total + 255) / 256, 256>>>(words, etype, eid, wtab, ttab, itab);
    }
    // 2. x-gates: XG[dir] = X @ Wih^T + b   (M=8192, N=512, K=140)
    {
        dim3 grid((G4 + BN - 1) / BN, (Ssz * Bsz + BM - 1) / BM);
        sgemm_kernel<<<grid, 256>>>(pX, INs, Wih_f, b_f, pXG, G4,
                                    Ssz * Bsz, G4, INs, 1, 0);
        sgemm_kernel<<<grid, 256>>>(pX, INs, Wih_b, b_b, pXG + (size_t)Ssz * Bsz * G4, G4,
                                    Ssz * Bsz, G4, INs, 1, 0);
    }
    // 3. BiLSTM recurrence (8 batch-groups x 2 directions, independent blocks)
    lstm_kernel<<<dim3(Bsz / 2, 2), 128>>>();
    // 4. masked cumsum
    cumsum_kernel<<<(Bsz * GD + 255) / 256, 256>>>(mask);
    // 5. span means -> feat[:, :, 0:256]
    span_kernel<<<Bsz * Nn, GD>>>(ginfo, gnum);
    // 6. adjacency normalization
    adj_kernel<<<Bsz * Nn, Nn>>>(adj, gnum);
    // 7. GCN layer 1: h1 = relu((Anorm @ gfea) @ W1 + b1) -> feat[:, :, 256:512]
    gcn_agg_kernel<<<Bsz * Nn, GD>>>(0);
    {
        dim3 grid((GD + BN - 1) / BN, (Bsz * Nn + BM - 1) / BM);
        sgemm_kernel<<<grid, 256>>>(pTmp, GD, gcn_W1, gcn_b1, pFeat + GD, BANK,
                                    Bsz * Nn, GD, GD, 0, 2);
    }
    //    GCN layer 2: h2 = relu((Anorm @ h1) @ W2 + b2) -> feat[:, :, 512:768]
    gcn_agg_kernel<<<Bsz * Nn, GD>>>(GD);
    {
        dim3 grid((GD + BN - 1) / BN, (Bsz * Nn + BM - 1) / BM);
        sgemm_kernel<<<grid, 256>>>(pTmp, GD, gcn_W2, gcn_b2, pFeat + 2 * GD, BANK,
                                    Bsz * Nn, GD, GD, 0, 2);
    }
    // 8. entity bank
    bank_kernel<<<Bsz * Ee, 256>>>(ginfo, gnum);
    // 9. rel features
    {
        size_t total = (size_t)Bsz * Pp * CLSZ;
        rel_kernel<<<(unsigned)((total + 255) / 256), 256>>>(pairs, dist, dtab);
    }
    // 10. MLP layer 1: hid = tanh(rel @ pW1 + pb1)   (M=8192, N=1536, K=1556)
    {
        dim3 grid((HID + BN - 1) / BN, (Bsz * Pp + BM - 1) / BM);
        sgemm_kernel<<<grid, 256>>>(pRel, CLSZ, pW1, pb1, pHid, HID,
                                    Bsz * Pp, HID, CLSZ, 0, 1);
    }
    // 11. MLP layer 2: scores = hid @ pW2 + pb2      (M=8192, N=97, K=1536)
    {
        dim3 grid((Rr + BN - 1) / BN, (Bsz * Pp + BM - 1) / BM);
        sgemm_kernel<<<grid, 256>>>(pHid, HID, pW2, pb2, out, Rr,
                                    Bsz * Pp, Rr, HID, 0, 0);
    }
}